// round 2
// baseline (speedup 1.0000x reference)
#include <cuda_runtime.h>

#define NN 50000
#define EE 800000
#define CC 128
#define SA 132              // padded smem row stride for activations (floats)
#define NTHR 512
#define NT_EDGE (EE/128)    // 6250 edge tiles

// ---------------- scratch (__device__ globals: allocation-free) ----------------
__device__ __align__(16) float g_q[(size_t)NN*CC];
__device__ __align__(16) float g_k[(size_t)NN*CC];
__device__ __align__(16) float g_v[(size_t)NN*CC];
__device__ __align__(16) float g_z[(size_t)NN*CC];
__device__ __align__(16) float g_num[(size_t)NN*CC];
__device__ __align__(16) float g_delta[(size_t)EE*CC];   // 409.6 MB streaming scratch
__device__ int g_is64;

// ---------------- packed f32x2 helpers (sm_103a dual-fp32 pipe) ----------------
__device__ __forceinline__ unsigned long long pk2(float lo, float hi){
  unsigned long long r;
  asm("mov.b64 %0, {%1,%2};" : "=l"(r) : "f"(lo), "f"(hi));
  return r;
}
__device__ __forceinline__ float2 up2(unsigned long long v){
  float2 f;
  asm("mov.b64 {%0,%1}, %2;" : "=f"(f.x), "=f"(f.y) : "l"(v));
  return f;
}
__device__ __forceinline__ void fma2(unsigned long long &d, unsigned long long a, unsigned long long b){
  asm("fma.rn.f32x2 %0, %1, %2, %0;" : "+l"(d) : "l"(a), "l"(b));
}

// ---------------- 128x128x128 tile GEMM: C = A * W ----------------
// A: smem [128][SA]. W: smem [128][128] (k-major, unpadded).
// 512 threads: tx=tid&15 (8 cols), ty=tid>>4 (4 rows). acc = 4 rows x 4 col-pairs.
__device__ __forceinline__ void gemm_tile(const float* __restrict__ As,
                                          const float* __restrict__ Ws,
                                          int m0, int n0,
                                          unsigned long long acc[4][4]){
  #pragma unroll
  for (int i=0;i<4;i++)
    #pragma unroll
    for (int j=0;j<4;j++) acc[i][j] = 0ULL;

  #pragma unroll 4
  for (int k=0;k<CC;k++){
    unsigned long long w[4];
    const float* wr = Ws + k*CC + n0;
    #pragma unroll
    for (int j=0;j<4;j++) w[j] = *(const unsigned long long*)(wr + 2*j);
    const float* ar = As + m0*SA + k;
    #pragma unroll
    for (int i=0;i<4;i++){
      float a = ar[i*SA];
      unsigned long long ad = pk2(a, a);
      #pragma unroll
      for (int j=0;j<4;j++) fma2(acc[i][j], ad, w[j]);
    }
  }
}

__device__ __forceinline__ void load_w128(float* Ws, const float* __restrict__ W, int tid){
  #pragma unroll
  for (int i = tid; i < 128*32; i += NTHR)
    ((float4*)Ws)[i] = ((const float4*)W)[i];
}

// relu(acc + bias) -> act buffer (in place safe: called after full GEMM drain + sync)
__device__ __forceinline__ void epi_relu_smem(unsigned long long acc[4][4],
                                              const float* __restrict__ bias,
                                              float* Bs, int m0, int n0){
  #pragma unroll
  for (int i=0;i<4;i++){
    #pragma unroll
    for (int j=0;j<4;j++){
      float2 p = up2(acc[i][j]);
      float2 o;
      o.x = fmaxf(p.x + bias[n0+2*j],   0.f);
      o.y = fmaxf(p.y + bias[n0+2*j+1], 0.f);
      *(float2*)(Bs + (m0+i)*SA + n0 + 2*j) = o;
    }
  }
}

__device__ __forceinline__ void store_plain(unsigned long long acc[4][4],
                                            float* out, int r0, int m0, int n0){
  #pragma unroll
  for (int i=0;i<4;i++){
    int r = r0 + m0 + i;
    if (r < NN){
      #pragma unroll
      for (int j=0;j<4;j++)
        *(float2*)(out + (size_t)r*CC + n0 + 2*j) = up2(acc[i][j]);
    }
  }
}

// ---------------- detect edge_index element width (int64 vs int32) ----------------
__global__ void detect_kernel(const void* __restrict__ ei){
  const unsigned long long* p = (const unsigned long long*)ei;
  int ok64 = 1;
  for (int i=0;i<64;i++){
    if ((p[i] >> 32) != 0ULL){ ok64 = 0; break; }
  }
  g_is64 = ok64;
}

__device__ __forceinline__ void load_idx(const void* __restrict__ ei, long long e0,
                                         int* si, int* di, int tid){
  if (tid < 128){
    if (g_is64){
      const long long* p = (const long long*)ei;
      si[tid] = (int)p[e0 + tid];
      di[tid] = (int)p[(long long)EE + e0 + tid];
    } else {
      const int* p = (const int*)ei;
      si[tid] = p[e0 + tid];
      di[tid] = p[(long long)EE + e0 + tid];
    }
  }
}

// ---------------- node kernel: h = relu(xW_in+b); q,k,v = h W_{dst,src,lin} ----------------
#define SM_NODE (2*128*SA*4 + 128*128*4)
__global__ void __launch_bounds__(NTHR,1)
node_qkv_kernel(const float* __restrict__ x,
                const float* __restrict__ W_in, const float* __restrict__ b_in,
                const float* __restrict__ W_dst, const float* __restrict__ W_src,
                const float* __restrict__ W_lin){
  extern __shared__ float sm[];
  float* As = sm;
  float* Bs = sm + 128*SA;
  float* Ws = sm + 2*128*SA;
  int tid = threadIdx.x;
  int tx = tid & 15, ty = tid >> 4;
  int m0 = ty*4, n0 = tx*8;
  int r0 = blockIdx.x * 128;

  load_w128(Ws, W_in, tid);
  #pragma unroll 1
  for (int i = tid; i < 128*32; i += NTHR){
    int r = i >> 5, c4 = i & 31;
    float4 v = make_float4(0.f,0.f,0.f,0.f);
    if (r0 + r < NN) v = *((const float4*)(x + (size_t)(r0+r)*CC) + c4);
    *(float4*)(As + r*SA + 4*c4) = v;
  }
  __syncthreads();

  unsigned long long acc[4][4];
  gemm_tile(As, Ws, m0, n0, acc);
  __syncthreads();
  epi_relu_smem(acc, b_in, Bs, m0, n0);
  load_w128(Ws, W_dst, tid);
  __syncthreads();

  gemm_tile(Bs, Ws, m0, n0, acc);
  store_plain(acc, g_q, r0, m0, n0);
  __syncthreads();
  load_w128(Ws, W_src, tid);
  __syncthreads();

  gemm_tile(Bs, Ws, m0, n0, acc);
  store_plain(acc, g_k, r0, m0, n0);
  __syncthreads();
  load_w128(Ws, W_lin, tid);
  __syncthreads();

  gemm_tile(Bs, Ws, m0, n0, acc);
  store_plain(acc, g_v, r0, m0, n0);
}

// ---------------- persistent pos kernel: delta = mlp2(pos[dst]-pos[src]) -> g_delta ----------------
#define SM_EDGE (2*128*128*4 + 128*SA*4 + 1024)
__global__ void __launch_bounds__(NTHR,1)
pos_kernel(const float* __restrict__ pos, const void* __restrict__ ei,
           const float* __restrict__ pw1, const float* __restrict__ pb1,
           const float* __restrict__ pw2, const float* __restrict__ pb2){
  extern __shared__ float sm[];
  float* W1 = sm;
  float* W2 = sm + 128*128;
  float* As = sm + 2*128*128;
  int* si = (int*)(As + 128*SA);
  int* di = si + 128;
  int tid = threadIdx.x;
  int tx = tid & 15, ty = tid >> 4;
  int m0 = ty*4, n0 = tx*8;

  load_w128(W1, pw1, tid);
  load_w128(W2, pw2, tid);

  for (int t = blockIdx.x; t < NT_EDGE; t += gridDim.x){
    long long e0 = (long long)t * 128;
    __syncthreads();                 // protect si/di + As from previous iter readers
    load_idx(ei, e0, si, di, tid);
    __syncthreads();

    // As = pos[dst] - pos[src]
    #pragma unroll 1
    for (int i = tid; i < 128*32; i += NTHR){
      int e = i >> 5, c4 = i & 31;
      float4 a = *((const float4*)(pos + (size_t)di[e]*CC) + c4);
      float4 b = *((const float4*)(pos + (size_t)si[e]*CC) + c4);
      *(float4*)(As + e*SA + 4*c4) = make_float4(a.x-b.x, a.y-b.y, a.z-b.z, a.w-b.w);
    }
    __syncthreads();

    unsigned long long acc[4][4];
    gemm_tile(As, W1, m0, n0, acc);
    __syncthreads();
    epi_relu_smem(acc, pb1, As, m0, n0);    // in-place
    __syncthreads();
    gemm_tile(As, W2, m0, n0, acc);

    // delta = relu(acc + pb2) -> g_delta (streaming)
    #pragma unroll
    for (int i=0;i<4;i++){
      float* dp = g_delta + (e0 + m0 + i)*CC + n0;
      #pragma unroll
      for (int j=0;j<2;j++){
        float2 p0 = up2(acc[i][2*j]);
        float2 p1 = up2(acc[i][2*j+1]);
        float4 o;
        o.x = fmaxf(p0.x + pb2[n0+4*j],   0.f);
        o.y = fmaxf(p0.y + pb2[n0+4*j+1], 0.f);
        o.z = fmaxf(p1.x + pb2[n0+4*j+2], 0.f);
        o.w = fmaxf(p1.y + pb2[n0+4*j+3], 0.f);
        *(float4*)(dp + 4*j) = o;
      }
    }
  }
}

// ---------------- persistent attn kernel: alpha MLP, exp, fused numerator+z reduction ----------------
__global__ void __launch_bounds__(NTHR,1)
attn_kernel(const void* __restrict__ ei,
            const float* __restrict__ aw1, const float* __restrict__ ab1,
            const float* __restrict__ aw2, const float* __restrict__ ab2){
  extern __shared__ float sm[];
  float* W1 = sm;
  float* W2 = sm + 128*128;
  float* As = sm + 2*128*128;
  int* si = (int*)(As + 128*SA);
  int* di = si + 128;
  int tid = threadIdx.x;
  int tx = tid & 15, ty = tid >> 4;
  int m0 = ty*4, n0 = tx*8;

  load_w128(W1, aw1, tid);
  load_w128(W2, aw2, tid);

  for (int t = blockIdx.x; t < NT_EDGE; t += gridDim.x){
    long long e0 = (long long)t * 128;
    __syncthreads();                 // epilogue readers of si/di done
    load_idx(ei, e0, si, di, tid);
    __syncthreads();

    // As = q[dst] - k[src] + delta
    #pragma unroll 1
    for (int i = tid; i < 128*32; i += NTHR){
      int e = i >> 5, c4 = i & 31;
      float4 qv = *((const float4*)(g_q + (size_t)di[e]*CC) + c4);
      float4 kv = *((const float4*)(g_k + (size_t)si[e]*CC) + c4);
      float4 dd = *((const float4*)(g_delta + (e0 + e)*CC) + c4);
      *(float4*)(As + e*SA + 4*c4) =
        make_float4(qv.x-kv.x+dd.x, qv.y-kv.y+dd.y, qv.z-kv.z+dd.z, qv.w-kv.w+dd.w);
    }
    __syncthreads();

    unsigned long long acc[4][4];
    gemm_tile(As, W1, m0, n0, acc);
    __syncthreads();
    epi_relu_smem(acc, ab1, As, m0, n0);    // in-place
    __syncthreads();
    gemm_tile(As, W2, m0, n0, acc);

    // alpha -> ea = exp(relu(alpha)); numerator p = ea*(v[src]+delta)
    #pragma unroll
    for (int i=0;i<4;i++){
      int m = m0 + i;
      const float* vr = g_v + (size_t)si[m]*CC + n0;
      const float* dl = g_delta + (e0 + m)*CC + n0;    // L2-hit (just read above)
      float ea[8], pp[8];
      #pragma unroll
      for (int j=0;j<4;j++){
        float2 a2 = up2(acc[i][j]);
        float al0 = fmaxf(a2.x + ab2[n0+2*j],   0.f);
        float al1 = fmaxf(a2.y + ab2[n0+2*j+1], 0.f);
        // alpha >= 0 and small: softmax without max-subtraction is exact here
        float e0f = __expf(al0), e1f = __expf(al1);
        float2 vv = *(const float2*)(vr + 2*j);
        float2 dv = *(const float2*)(dl + 2*j);
        ea[2*j]   = e0f;  ea[2*j+1]   = e1f;
        pp[2*j]   = e0f * (vv.x + dv.x);
        pp[2*j+1] = e1f * (vv.y + dv.y);
      }
      float* zp = g_z   + (size_t)di[m]*CC + n0;
      float* np = g_num + (size_t)di[m]*CC + n0;
      asm volatile("red.global.add.v4.f32 [%0], {%1,%2,%3,%4};"
                   :: "l"(zp),   "f"(ea[0]),"f"(ea[1]),"f"(ea[2]),"f"(ea[3]) : "memory");
      asm volatile("red.global.add.v4.f32 [%0], {%1,%2,%3,%4};"
                   :: "l"(zp+4), "f"(ea[4]),"f"(ea[5]),"f"(ea[6]),"f"(ea[7]) : "memory");
      asm volatile("red.global.add.v4.f32 [%0], {%1,%2,%3,%4};"
                   :: "l"(np),   "f"(pp[0]),"f"(pp[1]),"f"(pp[2]),"f"(pp[3]) : "memory");
      asm volatile("red.global.add.v4.f32 [%0], {%1,%2,%3,%4};"
                   :: "l"(np+4), "f"(pp[4]),"f"(pp[5]),"f"(pp[6]),"f"(pp[7]) : "memory");
    }
  }
}

// ---------------- output kernel: agg = num/z ; out = relu(agg W_out + b_out) ----------------
#define SM_OUT (128*SA*4 + 128*128*4)
__global__ void __launch_bounds__(NTHR,1)
out_kernel(const float* __restrict__ W_out, const float* __restrict__ b_out,
           float* __restrict__ out){
  extern __shared__ float sm[];
  float* As = sm;
  float* Ws = sm + 128*SA;
  int tid = threadIdx.x;
  int tx = tid & 15, ty = tid >> 4;
  int m0 = ty*4, n0 = tx*8;
  int r0 = blockIdx.x * 128;

  load_w128(Ws, W_out, tid);
  #pragma unroll 1
  for (int i = tid; i < 128*32; i += NTHR){
    int r = i >> 5, c4 = i & 31;
    float4 a = make_float4(0.f,0.f,0.f,0.f);
    if (r0 + r < NN){
      float4 nm = *((const float4*)(g_num + (size_t)(r0+r)*CC) + c4);
      float4 zz = *((const float4*)(g_z   + (size_t)(r0+r)*CC) + c4);
      a.x = nm.x / (zz.x + 1e-16f);
      a.y = nm.y / (zz.y + 1e-16f);
      a.z = nm.z / (zz.z + 1e-16f);
      a.w = nm.w / (zz.w + 1e-16f);
    }
    *(float4*)(As + r*SA + 4*c4) = a;
  }
  __syncthreads();

  unsigned long long acc[4][4];
  gemm_tile(As, Ws, m0, n0, acc);

  #pragma unroll
  for (int i=0;i<4;i++){
    int r = r0 + m0 + i;
    if (r < NN){
      #pragma unroll
      for (int j=0;j<4;j++){
        float2 p = up2(acc[i][j]);
        float2 o;
        o.x = fmaxf(p.x + b_out[n0+2*j],   0.f);
        o.y = fmaxf(p.y + b_out[n0+2*j+1], 0.f);
        *(float2*)(out + (size_t)r*CC + n0 + 2*j) = o;
      }
    }
  }
}

// ---------------- launch ----------------
extern "C" void kernel_launch(void* const* d_in, const int* in_sizes, int n_in,
                              void* d_out, int out_size){
  const float* x    = (const float*)d_in[0];
  const float* pos  = (const float*)d_in[1];
  const void*  ei   = d_in[2];
  const float* W_in = (const float*)d_in[3];
  const float* b_in = (const float*)d_in[4];
  const float* W_lin= (const float*)d_in[5];
  const float* W_src= (const float*)d_in[6];
  const float* W_dst= (const float*)d_in[7];
  const float* pw1  = (const float*)d_in[8];
  const float* pb1  = (const float*)d_in[9];
  const float* pw2  = (const float*)d_in[10];
  const float* pb2  = (const float*)d_in[11];
  const float* aw1  = (const float*)d_in[12];
  const float* ab1  = (const float*)d_in[13];
  const float* aw2  = (const float*)d_in[14];
  const float* ab2  = (const float*)d_in[15];
  const float* W_out= (const float*)d_in[16];
  const float* b_out= (const float*)d_in[17];

  static int nsm = 0;
  if (!nsm){
    cudaDeviceGetAttribute(&nsm, cudaDevAttrMultiProcessorCount, 0);
    if (nsm <= 0) nsm = 148;
    cudaFuncSetAttribute(node_qkv_kernel, cudaFuncAttributeMaxDynamicSharedMemorySize, SM_NODE);
    cudaFuncSetAttribute(pos_kernel,      cudaFuncAttributeMaxDynamicSharedMemorySize, SM_EDGE);
    cudaFuncSetAttribute(attn_kernel,     cudaFuncAttributeMaxDynamicSharedMemorySize, SM_EDGE);
    cudaFuncSetAttribute(out_kernel,      cudaFuncAttributeMaxDynamicSharedMemorySize, SM_OUT);
  }

  void *zp = nullptr, *np = nullptr;
  cudaGetSymbolAddress(&zp, g_z);
  cudaGetSymbolAddress(&np, g_num);
  cudaMemsetAsync(zp, 0, (size_t)NN*CC*sizeof(float), 0);
  cudaMemsetAsync(np, 0, (size_t)NN*CC*sizeof(float), 0);

  detect_kernel<<<1, 1>>>(ei);
  node_qkv_kernel<<<(NN+127)/128, NTHR, SM_NODE>>>(x, W_in, b_in, W_dst, W_src, W_lin);
  pos_kernel<<<nsm, NTHR, SM_EDGE>>>(pos, ei, pw1, pb1, pw2, pb2);
  attn_kernel<<<nsm, NTHR, SM_EDGE>>>(ei, aw1, ab1, aw2, ab2);
  out_kernel<<<(NN+127)/128, NTHR, SM_OUT>>>(W_out, b_out, (float*)d_out);
}

// round 3
// speedup vs baseline: 1.6344x; 1.6344x over previous
#include <cuda_runtime.h>

#define NN 50000
#define EE 800000
#define CC 128
#define SA 132              // padded smem row stride for activations (floats)
#define NTHR 512
#define NT_EDGE (EE/128)    // 6250 edge tiles

// ---------------- scratch (__device__ globals: allocation-free) ----------------
__device__ __align__(16) float g_q[(size_t)NN*CC];    // qa1 = h @ (W_dst@aw1)
__device__ __align__(16) float g_k[(size_t)NN*CC];    // ka1 = h @ (W_src@aw1)
__device__ __align__(16) float g_v[(size_t)NN*CC];
__device__ __align__(16) float g_pw[(size_t)NN*CC];   // posW1 = pos @ pw1
__device__ __align__(16) float g_z[(size_t)NN*CC];
__device__ __align__(16) float g_num[(size_t)NN*CC];
__device__ __align__(16) float g_Wqa[CC*CC];          // W_dst @ aw1
__device__ __align__(16) float g_Wka[CC*CC];          // W_src @ aw1
__device__ int g_is64;

// ---------------- packed f32x2 helpers ----------------
__device__ __forceinline__ unsigned long long pk2(float lo, float hi){
  unsigned long long r;
  asm("mov.b64 %0, {%1,%2};" : "=l"(r) : "f"(lo), "f"(hi));
  return r;
}
__device__ __forceinline__ float2 up2(unsigned long long v){
  float2 f;
  asm("mov.b64 {%0,%1}, %2;" : "=f"(f.x), "=f"(f.y) : "l"(v));
  return f;
}
__device__ __forceinline__ void fma2(unsigned long long &d, unsigned long long a, unsigned long long b){
  asm("fma.rn.f32x2 %0, %1, %2, %0;" : "+l"(d) : "l"(a), "l"(b));
}

// ---------------- cp.async helpers ----------------
__device__ __forceinline__ void cp16(float* sdst, const float* gsrc){
  unsigned s = (unsigned)__cvta_generic_to_shared(sdst);
  asm volatile("cp.async.cg.shared.global [%0], [%1], 16;" :: "r"(s), "l"(gsrc));
}
__device__ __forceinline__ void cpw_async(float* dst, const float* __restrict__ src, int tid){
  #pragma unroll
  for (int i = tid; i < CC*CC/4; i += NTHR) cp16(dst + 4*i, src + 4*i);
  asm volatile("cp.async.commit_group;");
}
#define CPWAIT1 asm volatile("cp.async.wait_group 1;")
#define CPWAIT0 asm volatile("cp.async.wait_group 0;")

// ---------------- 128x128x128 tile GEMM: C = A * W (bank-conflict-free) ----------------
// A: smem [128][SA]. W: smem [128][128].
// 512 threads: tx=tid&15, ty=tid>>4. Rows m0..m0+3 (m0=4*ty).
// Cols per thread: col-pair j at cb+32*j, cb=2*tx.
// w LDS.64: lane word idx = 2*tx+32*j -> banks 2tx,2tx+1: all 32 banks, conflict-free.
__device__ __forceinline__ void gemm_tile(const float* __restrict__ As,
                                          const float* __restrict__ Ws,
                                          int m0, int cb,
                                          unsigned long long acc[4][4]){
  #pragma unroll
  for (int i=0;i<4;i++)
    #pragma unroll
    for (int j=0;j<4;j++) acc[i][j] = 0ULL;

  #pragma unroll 2
  for (int k4=0;k4<CC;k4+=4){
    float4 a4[4];
    #pragma unroll
    for (int i=0;i<4;i++) a4[i] = *(const float4*)(As + (m0+i)*SA + k4);
    #pragma unroll
    for (int kk=0;kk<4;kk++){
      const float* wr = Ws + (k4+kk)*CC + cb;
      unsigned long long w[4];
      #pragma unroll
      for (int j=0;j<4;j++) w[j] = *(const unsigned long long*)(wr + 32*j);
      #pragma unroll
      for (int i=0;i<4;i++){
        float a = (kk==0)?a4[i].x:(kk==1)?a4[i].y:(kk==2)?a4[i].z:a4[i].w;
        unsigned long long ad = pk2(a,a);
        #pragma unroll
        for (int j=0;j<4;j++) fma2(acc[i][j], ad, w[j]);
      }
    }
  }
}

__device__ __forceinline__ void load_w128(float* Ws, const float* __restrict__ W, int tid){
  #pragma unroll
  for (int i = tid; i < CC*CC/4; i += NTHR)
    ((float4*)Ws)[i] = ((const float4*)W)[i];
}

__device__ __forceinline__ void load_a128(float* As, const float* __restrict__ A, int tid){
  #pragma unroll
  for (int i = tid; i < CC*32; i += NTHR){
    int r = i >> 5, c4 = i & 31;
    *(float4*)(As + r*SA + 4*c4) = ((const float4*)A)[i];
  }
}

// relu(acc + bias) -> smem act buffer (strided cols)
__device__ __forceinline__ void epi_relu_smem(unsigned long long acc[4][4],
                                              const float* __restrict__ bias,
                                              float* Bs, int m0, int cb){
  #pragma unroll
  for (int i=0;i<4;i++){
    #pragma unroll
    for (int j=0;j<4;j++){
      int c = cb + 32*j;
      float2 p = up2(acc[i][j]);
      float2 b = *(const float2*)(bias + c);
      float2 o;
      o.x = fmaxf(p.x + b.x, 0.f);
      o.y = fmaxf(p.y + b.y, 0.f);
      *(float2*)(Bs + (m0+i)*SA + c) = o;
    }
  }
}

__device__ __forceinline__ void store_plain(unsigned long long acc[4][4],
                                            float* out, int r0, int m0, int cb){
  #pragma unroll
  for (int i=0;i<4;i++){
    int r = r0 + m0 + i;
    if (r < NN){
      #pragma unroll
      for (int j=0;j<4;j++)
        *(float2*)(out + (size_t)r*CC + cb + 32*j) = up2(acc[i][j]);
    }
  }
}

// ---------------- detect edge_index element width ----------------
__global__ void detect_kernel(const void* __restrict__ ei){
  const unsigned long long* p = (const unsigned long long*)ei;
  int ok64 = 1;
  for (int i=0;i<64;i++){
    if ((p[i] >> 32) != 0ULL){ ok64 = 0; break; }
  }
  g_is64 = ok64;
}

__device__ __forceinline__ void load_idx(const void* __restrict__ ei, long long e0,
                                         int* si, int* di, int tid){
  if (tid < 128){
    if (g_is64){
      const long long* p = (const long long*)ei;
      si[tid] = (int)p[e0 + tid];
      di[tid] = (int)p[(long long)EE + e0 + tid];
    } else {
      const int* p = (const int*)ei;
      si[tid] = p[e0 + tid];
      di[tid] = p[(long long)EE + e0 + tid];
    }
  }
}

// ---------------- composite weight kernel: g_Wqa = W_dst@aw1, g_Wka = W_src@aw1 ----------------
#define SM_COMP (CC*SA*4 + CC*CC*4)
__global__ void __launch_bounds__(NTHR,1)
comp_kernel(const float* __restrict__ W_dst, const float* __restrict__ W_src,
            const float* __restrict__ aw1){
  extern __shared__ float sm[];
  float* As = sm;
  float* Ws = sm + CC*SA;
  int tid = threadIdx.x;
  int tx = tid & 15, ty = tid >> 4;
  int m0 = ty*4, cb = 2*tx;
  const float* A = blockIdx.x ? W_src : W_dst;
  float* out = blockIdx.x ? g_Wka : g_Wqa;

  load_a128(As, A, tid);
  load_w128(Ws, aw1, tid);
  __syncthreads();
  unsigned long long acc[4][4];
  gemm_tile(As, Ws, m0, cb, acc);
  #pragma unroll
  for (int i=0;i<4;i++)
    #pragma unroll
    for (int j=0;j<4;j++)
      *(float2*)(out + (m0+i)*CC + cb + 32*j) = up2(acc[i][j]);
}

// ---------------- node kernel: h, v, qa1, ka1, posW1 ----------------
#define SM_NODE (2*CC*SA*4 + CC*CC*4)
__global__ void __launch_bounds__(NTHR,1)
node_kernel(const float* __restrict__ x, const float* __restrict__ pos,
            const float* __restrict__ W_in, const float* __restrict__ b_in,
            const float* __restrict__ W_lin, const float* __restrict__ pw1){
  extern __shared__ float sm[];
  float* As = sm;
  float* Bs = sm + CC*SA;
  float* Ws = sm + 2*CC*SA;
  int tid = threadIdx.x;
  int tx = tid & 15, ty = tid >> 4;
  int m0 = ty*4, cb = 2*tx;
  int r0 = blockIdx.x * 128;

  load_w128(Ws, W_in, tid);
  #pragma unroll 1
  for (int i = tid; i < CC*32; i += NTHR){
    int r = i >> 5, c4 = i & 31;
    float4 v = make_float4(0.f,0.f,0.f,0.f);
    if (r0 + r < NN) v = *((const float4*)(x + (size_t)(r0+r)*CC) + c4);
    *(float4*)(As + r*SA + 4*c4) = v;
  }
  __syncthreads();

  unsigned long long acc[4][4];
  gemm_tile(As, Ws, m0, cb, acc);           // x @ W_in
  __syncthreads();
  epi_relu_smem(acc, b_in, Bs, m0, cb);     // h
  load_w128(Ws, W_lin, tid);
  __syncthreads();

  gemm_tile(Bs, Ws, m0, cb, acc);           // v
  store_plain(acc, g_v, r0, m0, cb);
  __syncthreads();
  load_w128(Ws, g_Wqa, tid);
  __syncthreads();

  gemm_tile(Bs, Ws, m0, cb, acc);           // qa1
  store_plain(acc, g_q, r0, m0, cb);
  __syncthreads();
  load_w128(Ws, g_Wka, tid);
  __syncthreads();

  gemm_tile(Bs, Ws, m0, cb, acc);           // ka1
  store_plain(acc, g_k, r0, m0, cb);
  __syncthreads();

  load_w128(Ws, pw1, tid);
  #pragma unroll 1
  for (int i = tid; i < CC*32; i += NTHR){
    int r = i >> 5, c4 = i & 31;
    float4 v = make_float4(0.f,0.f,0.f,0.f);
    if (r0 + r < NN) v = *((const float4*)(pos + (size_t)(r0+r)*CC) + c4);
    *(float4*)(As + r*SA + 4*c4) = v;
  }
  __syncthreads();

  gemm_tile(As, Ws, m0, cb, acc);           // posW1
  store_plain(acc, g_pw, r0, m0, cb);
}

// ---------------- merged persistent edge kernel: 3 GEMMs + softmax-numerator ----------------
#define SM_EDGE (2*CC*CC*4 + CC*SA*4 + 1024)
__global__ void __launch_bounds__(NTHR,1)
edge_kernel(const void* __restrict__ ei,
            const float* __restrict__ pb1, const float* __restrict__ pw2,
            const float* __restrict__ pb2,
            const float* __restrict__ aw1, const float* __restrict__ ab1,
            const float* __restrict__ aw2, const float* __restrict__ ab2){
  extern __shared__ float sm[];
  float* WB0 = sm;
  float* WB1 = sm + CC*CC;
  float* As  = sm + 2*CC*CC;
  int* si = (int*)(As + CC*SA);
  int* di = si + 128;
  int tid = threadIdx.x;
  int tx = tid & 15, ty = tid >> 4;
  int m0 = ty*4, cb = 2*tx;

  float* WB[2] = {WB0, WB1};

  // prologue: pw2 for first tile into WB0
  cpw_async(WB[0], pw2, tid);
  int it = 0;

  for (int t = blockIdx.x; t < NT_EDGE; t += gridDim.x, it++){
    int b = it & 1;           // pw2 lives in WB[b] this tile
    long long e0 = (long long)t * 128;

    __syncthreads();                               // S0: prev tile done with As/si/di
    load_idx(ei, e0, si, di, tid);
    cpw_async(WB[b^1], aw1, tid);                  // in flight: {pw2, aw1}
    CPWAIT1;                                       // pw2 arrived (this thread)
    __syncthreads();                               // publish idx before gather reads

    // phase A: As = relu(posW1[dst] - posW1[src] + pb1)
    #pragma unroll 1
    for (int i = tid; i < CC*32; i += NTHR){
      int e = i >> 5, c4 = i & 31;
      float4 a = *((const float4*)(g_pw + (size_t)di[e]*CC) + c4);
      float4 bch = *((const float4*)(g_pw + (size_t)si[e]*CC) + c4);
      float4 bb = __ldg((const float4*)(pb1) + c4);
      float4 o;
      o.x = fmaxf(a.x - bch.x + bb.x, 0.f);
      o.y = fmaxf(a.y - bch.y + bb.y, 0.f);
      o.z = fmaxf(a.z - bch.z + bb.z, 0.f);
      o.w = fmaxf(a.w - bch.w + bb.w, 0.f);
      *(float4*)(As + e*SA + 4*c4) = o;
    }
    __syncthreads();                               // S1: As + pw2 ready (all threads)

    unsigned long long acc[4][4];
    gemm_tile(As, WB[b], m0, cb, acc);             // GEMM1: @pw2
    __syncthreads();                               // S2: GEMM1 readers done (As, WB[b] free)

    // delta = relu(acc + pb2) -> regs + As (in place)
    float2 dlt[4][4];
    #pragma unroll
    for (int i=0;i<4;i++){
      #pragma unroll
      for (int j=0;j<4;j++){
        int c = cb + 32*j;
        float2 p = up2(acc[i][j]);
        float2 bb = *(const float2*)(pb2 + c);
        dlt[i][j].x = fmaxf(p.x + bb.x, 0.f);
        dlt[i][j].y = fmaxf(p.y + bb.y, 0.f);
        *(float2*)(As + (m0+i)*SA + c) = dlt[i][j];
      }
    }
    cpw_async(WB[b], aw2, tid);                    // in flight: {aw1, aw2}
    CPWAIT1;                                       // aw1 arrived
    __syncthreads();                               // S3

    gemm_tile(As, WB[b^1], m0, cb, acc);           // GEMM2: delta @ aw1
    __syncthreads();                               // S4: GEMM2 readers done

    // phase C: As = relu(acc + qa1[dst] - ka1[src] + ab1)
    #pragma unroll
    for (int i=0;i<4;i++){
      int m = m0 + i;
      const float* qr = g_q + (size_t)di[m]*CC;
      const float* kr = g_k + (size_t)si[m]*CC;
      #pragma unroll
      for (int j=0;j<4;j++){
        int c = cb + 32*j;
        float2 p = up2(acc[i][j]);
        float2 qv = *(const float2*)(qr + c);
        float2 kv = *(const float2*)(kr + c);
        float2 bb = *(const float2*)(ab1 + c);
        float2 o;
        o.x = fmaxf(p.x + qv.x - kv.x + bb.x, 0.f);
        o.y = fmaxf(p.y + qv.y - kv.y + bb.y, 0.f);
        *(float2*)(As + m*SA + c) = o;
      }
    }
    cpw_async(WB[b^1], pw2, tid);                  // next tile; in flight: {aw2, pw2'}
    CPWAIT1;                                       // aw2 arrived
    __syncthreads();                               // S5

    gemm_tile(As, WB[b], m0, cb, acc);             // GEMM3: @aw2

    // epilogue: alpha -> ea = exp(relu(alpha)); numerator = ea*(v[src]+delta)
    #pragma unroll
    for (int i=0;i<4;i++){
      int m = m0 + i;
      const float* vr = g_v + (size_t)si[m]*CC;
      float* zp = g_z   + (size_t)di[m]*CC;
      float* np = g_num + (size_t)di[m]*CC;
      #pragma unroll
      for (int j=0;j<4;j++){
        int c = cb + 32*j;
        float2 a2 = up2(acc[i][j]);
        float2 bb = *(const float2*)(ab2 + c);
        float al0 = fmaxf(a2.x + bb.x, 0.f);
        float al1 = fmaxf(a2.y + bb.y, 0.f);
        // alpha >= 0 and small: softmax without max-subtraction is exact here
        float ex0 = __expf(al0), ex1 = __expf(al1);
        float2 vv = *(const float2*)(vr + c);
        float p0 = ex0 * (vv.x + dlt[i][j].x);
        float p1 = ex1 * (vv.y + dlt[i][j].y);
        asm volatile("red.global.add.v2.f32 [%0], {%1,%2};"
                     :: "l"(zp + c), "f"(ex0), "f"(ex1) : "memory");
        asm volatile("red.global.add.v2.f32 [%0], {%1,%2};"
                     :: "l"(np + c), "f"(p0), "f"(p1) : "memory");
      }
    }
  }
}

// ---------------- output kernel: agg = num/z ; out = relu(agg W_out + b_out) ----------------
#define SM_OUT (CC*SA*4 + CC*CC*4)
__global__ void __launch_bounds__(NTHR,1)
out_kernel(const float* __restrict__ W_out, const float* __restrict__ b_out,
           float* __restrict__ out){
  extern __shared__ float sm[];
  float* As = sm;
  float* Ws = sm + CC*SA;
  int tid = threadIdx.x;
  int tx = tid & 15, ty = tid >> 4;
  int m0 = ty*4, cb = 2*tx;
  int r0 = blockIdx.x * 128;

  load_w128(Ws, W_out, tid);
  #pragma unroll 1
  for (int i = tid; i < CC*32; i += NTHR){
    int r = i >> 5, c4 = i & 31;
    float4 a = make_float4(0.f,0.f,0.f,0.f);
    if (r0 + r < NN){
      float4 nm = *((const float4*)(g_num + (size_t)(r0+r)*CC) + c4);
      float4 zz = *((const float4*)(g_z   + (size_t)(r0+r)*CC) + c4);
      a.x = nm.x / (zz.x + 1e-16f);
      a.y = nm.y / (zz.y + 1e-16f);
      a.z = nm.z / (zz.z + 1e-16f);
      a.w = nm.w / (zz.w + 1e-16f);
    }
    *(float4*)(As + r*SA + 4*c4) = a;
  }
  __syncthreads();

  unsigned long long acc[4][4];
  gemm_tile(As, Ws, m0, cb, acc);

  #pragma unroll
  for (int i=0;i<4;i++){
    int r = r0 + m0 + i;
    if (r < NN){
      #pragma unroll
      for (int j=0;j<4;j++){
        int c = cb + 32*j;
        float2 p = up2(acc[i][j]);
        float2 bb = *(const float2*)(b_out + c);
        float2 o;
        o.x = fmaxf(p.x + bb.x, 0.f);
        o.y = fmaxf(p.y + bb.y, 0.f);
        *(float2*)(out + (size_t)r*CC + c) = o;
      }
    }
  }
}

// ---------------- launch ----------------
extern "C" void kernel_launch(void* const* d_in, const int* in_sizes, int n_in,
                              void* d_out, int out_size){
  const float* x    = (const float*)d_in[0];
  const float* pos  = (const float*)d_in[1];
  const void*  ei   = d_in[2];
  const float* W_in = (const float*)d_in[3];
  const float* b_in = (const float*)d_in[4];
  const float* W_lin= (const float*)d_in[5];
  const float* W_src= (const float*)d_in[6];
  const float* W_dst= (const float*)d_in[7];
  const float* pw1  = (const float*)d_in[8];
  const float* pb1  = (const float*)d_in[9];
  const float* pw2  = (const float*)d_in[10];
  const float* pb2  = (const float*)d_in[11];
  const float* aw1  = (const float*)d_in[12];
  const float* ab1  = (const float*)d_in[13];
  const float* aw2  = (const float*)d_in[14];
  const float* ab2  = (const float*)d_in[15];
  const float* W_out= (const float*)d_in[16];
  const float* b_out= (const float*)d_in[17];

  static int nsm = 0;
  if (!nsm){
    cudaDeviceGetAttribute(&nsm, cudaDevAttrMultiProcessorCount, 0);
    if (nsm <= 0) nsm = 148;
    cudaFuncSetAttribute(comp_kernel, cudaFuncAttributeMaxDynamicSharedMemorySize, SM_COMP);
    cudaFuncSetAttribute(node_kernel, cudaFuncAttributeMaxDynamicSharedMemorySize, SM_NODE);
    cudaFuncSetAttribute(edge_kernel, cudaFuncAttributeMaxDynamicSharedMemorySize, SM_EDGE);
    cudaFuncSetAttribute(out_kernel,  cudaFuncAttributeMaxDynamicSharedMemorySize, SM_OUT);
  }

  void *zp = nullptr, *np = nullptr;
  cudaGetSymbolAddress(&zp, g_z);
  cudaGetSymbolAddress(&np, g_num);
  cudaMemsetAsync(zp, 0, (size_t)NN*CC*sizeof(float), 0);
  cudaMemsetAsync(np, 0, (size_t)NN*CC*sizeof(float), 0);

  detect_kernel<<<1, 1>>>(ei);
  comp_kernel<<<2, NTHR, SM_COMP>>>(W_dst, W_src, aw1);
  node_kernel<<<(NN+127)/128, NTHR, SM_NODE>>>(x, pos, W_in, b_in, W_lin, pw1);
  edge_kernel<<<nsm, NTHR, SM_EDGE>>>(ei, pb1, pw2, pb2, aw1, ab1, aw2, ab2);
  out_kernel<<<(NN+127)/128, NTHR, SM_OUT>>>(W_out, b_out, (float*)d_out);
}